// round 9
// baseline (speedup 1.0000x reference)
#include <cuda_runtime.h>

#define NQ 13
#define FULL 0xffffffffu

// Transfer-matrix contraction (bond dim 4, Hermitian-reduced).
// One warp per batch element, 8 warps per CTA.
//   - lanes 0..12:  layer-1 params (phi, kappa) for wire l   (3 sincosf)
//   - lanes 16..28: layer-2 params (m, mu) for wire l-16     (2 sincosf)
//   - ALL 104 broadcast shuffles are pre-staged into register arrays so the
//     13-step chain is a pure FFMA dependency ladder (no SHFL latency inside)
//   - ev[q] kept by lane q -> one coalesced store.
__global__ __launch_bounds__(256, 1)
void qsim_tn(const float* __restrict__ x,
             const float* __restrict__ wts,
             float* __restrict__ out,
             int n)
{
    const int e = blockIdx.x * 8 + (threadIdx.x >> 5);
    const int l = threadIdx.x & 31;
    if (e >= n) return;

    // ---- per-lane gate parameters ----
    float p0x = 0.f, p0y = 0.f, p1x = 0.f, p1y = 0.f, kap = 0.f;
    float m = 0.f, mux = 0.f, muy = 0.f;

    if (l < NQ) {
        const float xv = __ldg(&x[e * NQ + l]);
        const float w0 = __ldg(&wts[l * 3 + 0]);
        const float w1 = __ldg(&wts[l * 3 + 1]);
        const float w2 = __ldg(&wts[l * 3 + 2]);
        float s1, c1, s2, c2, sp, cp;
        __sincosf(0.5f * xv * w0, &s1, &c1);   // RX half
        __sincosf(0.5f * xv * w1, &s2, &c2);   // RY half
        __sincosf(0.5f * w2,      &sp, &cp);   // RZ half
        const float A = c2 * c1, B = s2 * s1, C = s2 * c1, D = c2 * s1;
        p0x = fmaf(cp, A,  sp * B);
        p0y = fmaf(cp, B, -sp * A);
        p1x = fmaf(cp, C,  sp * D);
        p1y = fmaf(sp, C, -cp * D);
        kap = 2.f * fmaf(p0x, p1x, p0y * p1y);
    } else if (l >= 16 && l < 16 + NQ) {
        const int q = l - 16;
        const float xv = __ldg(&x[e * NQ + q]);
        const float w0 = __ldg(&wts[(NQ + q) * 3 + 0]);
        const float w1 = __ldg(&wts[(NQ + q) * 3 + 1]);
        float sa, ca, sb, cb;
        __sincosf(xv * w0, &sa, &ca);          // full angles (RZ cancels in M)
        __sincosf(xv * w1, &sb, &cb);
        m   = ca * cb;
        mux = -sb;
        muy = -sa * cb;
    }

    // ---- pre-stage ALL broadcasts into register arrays (pipelined SHFLs) ----
    float G0x[NQ], G0y[NQ], G1x[NQ], G1y[NQ], GK[NQ], GM[NQ], GUx[NQ], GUy[NQ];
    #pragma unroll
    for (int q = 0; q < NQ; q++) {
        G0x[q] = __shfl_sync(FULL, p0x, q);
        G0y[q] = __shfl_sync(FULL, p0y, q);
        G1x[q] = __shfl_sync(FULL, p1x, q);
        G1y[q] = __shfl_sync(FULL, p1y, q);
        GK[q]  = __shfl_sync(FULL, kap, q);
        GM[q]  = __shfl_sync(FULL, m,   16 + q);
        GUx[q] = __shfl_sync(FULL, mux, 16 + q);
        GUy[q] = __shfl_sync(FULL, muy, 16 + q);
    }

    // ---- pure-FFMA sequential chain ----
    float v00, v11, v01x, v01y;
    float my_ev = 0.f;
    {
        const float g0x = G0x[0], g0y = G0y[0], g1x = G1x[0], g1y = G1y[0];
        const float gm = GM[0], gux = GUx[0], guy = GUy[0];
        v00  =  gm * fmaf(g0x, g0x, g0y * g0y);
        v11  = -gm * fmaf(g1x, g1x, g1y * g1y);
        const float tx = fmaf(g0x, g1x,  g0y * g1y);   // conj(p0)*p1
        const float ty = fmaf(g0x, g1y, -g0y * g1x);
        v01x = fmaf(gux, tx, -guy * ty);
        v01y = fmaf(gux, ty,  guy * tx);
    }

    #pragma unroll
    for (int q = 1; q < NQ; q++) {
        const float g0x = G0x[q], g0y = G0y[q], g1x = G1x[q], g1y = G1y[q];
        const float gm = GM[q], gux = GUx[q], guy = GUy[q];

        {   // emit ev[q-1] using boundary kappa of wire q
            const float ev = v00 + v11 + GK[q] * (2.f * v01x);
            if (l == q - 1) my_ev = ev;
        }

        // h(c,a') = sum_{c'} phi(a'^c') v(c,c')
        const float h00x = fmaf(g0x, v00, fmaf(g1x, v01x, -g1y * v01y));
        const float h00y = fmaf(g0y, v00, fmaf(g1x, v01y,  g1y * v01x));
        const float h01x = fmaf(g1x, v00, fmaf(g0x, v01x, -g0y * v01y));
        const float h01y = fmaf(g1y, v00, fmaf(g0x, v01y,  g0y * v01x));
        const float h10x = fmaf(g1x, v11, fmaf(g0x, v01x,  g0y * v01y));
        const float h10y = fmaf(g1y, v11, fmaf(g0y, v01x, -g0x * v01y));
        const float h11x = fmaf(g0x, v11, fmaf(g1x, v01x,  g1y * v01y));
        const float h11y = fmaf(g0y, v11, fmaf(g1y, v01x, -g1x * v01y));
        // w(a,a') = sum_c conj(phi(a^c)) h(c,a')
        const float w00  = fmaf(g0x, h00x, g0y * h00y) + fmaf(g1x, h10x, g1y * h10y);
        const float w01x = fmaf(g0x, h01x, g0y * h01y) + fmaf(g1x, h11x, g1y * h11y);
        const float w01y = fmaf(g0x, h01y, -g0y * h01x) + fmaf(g1x, h11y, -g1y * h11x);
        const float w11  = fmaf(g1x, h01x, g1y * h01y) + fmaf(g0x, h11x, g0y * h11y);
        // v_new = M .* w
        v00  =  gm * w00;
        v11  = -gm * w11;
        v01x = fmaf(gux, w01x, -guy * w01y);
        v01y = fmaf(gux, w01y,  guy * w01x);
    }

    {
        const float ev = v00 + v11 + 2.f * v01x;
        if (l == NQ - 1) my_ev = ev;
    }

    if (l < NQ) out[e * NQ + l] = my_ev;
}

extern "C" void kernel_launch(void* const* d_in, const int* in_sizes, int n_in,
                              void* d_out, int out_size)
{
    const float* x = (const float*)d_in[0];   // (B, 13) float32
    const float* w = (const float*)d_in[1];   // (2, 13, 3) float32
    float* out     = (float*)d_out;           // (B, 13) float32

    const int B = in_sizes[0] / NQ;           // 512
    const int blocks = (B + 7) / 8;           // 64 CTAs x 256 threads
    qsim_tn<<<blocks, 256>>>(x, w, out, B);
}